// round 15
// baseline (speedup 1.0000x reference)
#include <cuda_runtime.h>
#include <math.h>

#define BS 64
#define Qn 1024
#define Tn 128
#define NCn 20
#define FINF 1e30f
#define KPL 32   // columns per lane (Qn / 32)

// Scratch (allocation-free rule: __device__ globals)
__device__ float g_prob[(size_t)BS * NCn * Qn];   // softmax probs, transposed (b, c, q)
__device__ float g_cost[(size_t)BS * Tn * Qn];    // cost, rows = targets, cols = queries

// ---------------------------------------------------------------------------
// XLA:CPU GenerateVF32Exp (Cephes/Eigen constants, HORNER) with LLVM FMA
// contraction as emitted on aarch64 (fmla/fmls).
// ---------------------------------------------------------------------------
__device__ __forceinline__ float expf_xla_fma(float x) {
    const float half   = 0.5f;
    const float one    = 1.0f;
    const float exp_hi = 88.3762626647950f;
    const float exp_lo = -88.3762626647949f;
    const float LOG2EF = 1.44269504088896341f;
    const float C1     = 0.693359375f;           // exact
    const float C2     = -2.12194440e-4f;
    const float p0     = 1.9875691500E-4f;
    const float p1     = 1.3981999507E-3f;
    const float p2     = 8.3334519073E-3f;
    const float p3     = 4.1665795894E-2f;
    const float p4     = 1.6666665459E-1f;
    const float p5     = 5.0000001201E-1f;

    float xc = fminf(fmaxf(x, exp_lo), exp_hi);
    float fx = floorf(__fmaf_rn(xc, LOG2EF, half));      // fma(x, log2e, 0.5)
    float xr = __fmaf_rn(-fx, C1, xc);                   // fmls: x - fx*C1
    xr       = __fmaf_rn(-fx, C2, xr);                   // fmls: .. - fx*C2
    float z  = __fmul_rn(xr, xr);

    float y = __fmaf_rn(p0, xr, p1);                     // fused Horner
    y = __fmaf_rn(y, xr, p2);
    y = __fmaf_rn(y, xr, p3);
    y = __fmaf_rn(y, xr, p4);
    y = __fmaf_rn(y, xr, p5);
    y = __fmaf_rn(y, z, xr);                             // y*z + x fused
    y = __fadd_rn(y, one);

    int emm0 = ((int)fx + 127) << 23;
    float pow2 = __int_as_float(emm0);
    return fmaxf(__fmul_rn(y, pow2), x);
}

// ---------------------------------------------------------------------------
// Kernel A: softmax over NC=20, stored transposed (b, class, q).
// exp = Cephes-Horner-FMA (XLA); sum = VF4 strided partials + NEON FADDP
// horizontal pairing (a0+a1)+(a2+a3); div = IEEE .rn.
// ---------------------------------------------------------------------------
__global__ void softmax_kernel(const float* __restrict__ logits) {
    int b = blockIdx.x;
    for (int q = threadIdx.x; q < Qn; q += blockDim.x) {
        const float* l = logits + ((size_t)b * Qn + q) * NCn;
        float lv[NCn];
        float m = -FINF;
#pragma unroll
        for (int c = 0; c < NCn; c++) { lv[c] = l[c]; m = fmaxf(m, lv[c]); }
#pragma unroll
        for (int c = 0; c < NCn; c++)
            lv[c] = expf_xla_fma(__fsub_rn(lv[c], m));

        // VF=4 vectorized reduce: 5 full quads, lane-wise accumulate
        float a0 = lv[0], a1 = lv[1], a2 = lv[2], a3 = lv[3];
#pragma unroll
        for (int i = 1; i < 5; i++) {
            a0 = __fadd_rn(a0, lv[4 * i + 0]);
            a1 = __fadd_rn(a1, lv[4 * i + 1]);
            a2 = __fadd_rn(a2, lv[4 * i + 2]);
            a3 = __fadd_rn(a3, lv[4 * i + 3]);
        }
        // NEON FADDP horizontal reduce: (a0+a1) + (a2+a3)
        float s = __fadd_rn(__fadd_rn(a0, a1), __fadd_rn(a2, a3));

#pragma unroll
        for (int c = 0; c < NCn; c++)
            g_prob[((size_t)b * NCn + c) * Qn + q] = __fdiv_rn(lv[c], s);  // IEEE div
    }
}

// ---------------------------------------------------------------------------
// Kernel B: cost[b][t][q] = (|pcx-tx| + |pcy-ty|) - prob[b][label_t][q]
// ---------------------------------------------------------------------------
__global__ void cost_kernel(const float* __restrict__ pred_coords,
                            const int*   __restrict__ tgt_labels,
                            const float* __restrict__ tgt_joints) {
    int t = blockIdx.x;
    int b = blockIdx.y;
    float tx  = tgt_joints[((size_t)b * Tn + t) * 2 + 0];
    float ty  = tgt_joints[((size_t)b * Tn + t) * 2 + 1];
    int   lbl = tgt_labels[(size_t)b * Tn + t];
    const float*  pr  = g_prob + ((size_t)b * NCn + lbl) * Qn;
    const float2* pcv = (const float2*)(pred_coords + (size_t)b * Qn * 2);
    float* out = g_cost + ((size_t)b * Tn + t) * Qn;
    for (int q = threadIdx.x; q < Qn; q += blockDim.x) {
        float2 p = pcv[q];
        float bbox = __fadd_rn(fabsf(__fsub_rn(p.x, tx)), fabsf(__fsub_rn(p.y, ty)));
        out[q] = __fsub_rn(bbox, pr[q]);
    }
}

// ---------------------------------------------------------------------------
// Kernel C: per-batch rectangular JV LSA — ONE WARP per batch.
// Lane L owns columns j = k*32 + L (k = 0..31): v, spc, SC in registers.
// ---------------------------------------------------------------------------
__global__ void __launch_bounds__(32, 1) lsa_kernel(float* __restrict__ out) {
    __shared__ float s_u[Tn];
    __shared__ int   s_col4row[Tn];
    __shared__ int   s_row4col[Qn];
    __shared__ int   s_path[Qn];

    const int b    = blockIdx.x;
    const int lane = threadIdx.x;
    const float* __restrict__ C = g_cost + (size_t)b * Tn * Qn;

    float v[KPL], spc[KPL];
#pragma unroll
    for (int k = 0; k < KPL; k++) v[k] = 0.f;

    for (int j = lane; j < Qn; j += 32) s_row4col[j] = -1;
    for (int t = lane; t < Tn; t += 32) { s_u[t] = 0.f; s_col4row[t] = -1; }
    __syncwarp();

    for (int cur = 0; cur < Tn; cur++) {
        unsigned SC = 0u;
#pragma unroll
        for (int k = 0; k < KPL; k++) spc[k] = FINF;

        int   i    = cur;
        float minV = 0.f;
        int   sink;

        while (true) {
            const float u_i = s_u[i];
            const float* __restrict__ Crow = C + (size_t)i * Qn;

            float bv = FINF;
            int   bj = 0x7fffffff;
#pragma unroll
            for (int k = 0; k < KPL; k++) {
                if (!((SC >> k) & 1u)) {
                    int j = k * 32 + lane;
                    float r = __fsub_rn(__fsub_rn(__fadd_rn(minV, __ldg(Crow + j)), u_i), v[k]);
                    if (r < spc[k]) { spc[k] = r; s_path[j] = i; }
                    if (spc[k] < bv) { bv = spc[k]; bj = j; }
                }
            }
#pragma unroll
            for (int off = 16; off; off >>= 1) {
                float ov = __shfl_down_sync(0xffffffffu, bv, off);
                int   oj = __shfl_down_sync(0xffffffffu, bj, off);
                if (ov < bv || (ov == bv && oj < bj)) { bv = ov; bj = oj; }
            }
            const int   jstar = __shfl_sync(0xffffffffu, bj, 0);
            const float mval  = __shfl_sync(0xffffffffu, bv, 0);

            if (lane == (jstar & 31)) SC |= 1u << (jstar >> 5);
            minV = mval;
            __syncwarp();
            int inext = s_row4col[jstar];
            if (inext < 0) { sink = jstar; break; }
            i = inext;
        }

        const float minVal = minV;

#pragma unroll
        for (int k = 0; k < KPL; k++) {
            if ((SC >> k) & 1u) {
                int   j = k * 32 + lane;
                float d = __fsub_rn(minVal, spc[k]);
                v[k] = __fsub_rn(v[k], d);
                int r = s_row4col[j];
                if (r >= 0) s_u[r] = __fadd_rn(s_u[r], d);
            }
        }
        __syncwarp();

        if (lane == 0) {
            s_u[cur] = __fadd_rn(s_u[cur], minVal);
            int jj = sink;
            while (true) {
                int ii = s_path[jj];
                s_row4col[jj] = ii;
                int nj = s_col4row[ii];
                s_col4row[ii] = jj;
                if (ii == cur) break;
                jj = nj;
            }
        }
        __syncwarp();
    }

    for (int t = lane; t < Tn; t += 32) {
        int c = s_col4row[t];
        int rank = 0;
#pragma unroll 4
        for (int s = 0; s < Tn; s++) rank += (s_col4row[s] < c);
        out[(size_t)b * Tn + rank]                   = (float)c;   // pred_idx
        out[(size_t)BS * Tn + (size_t)b * Tn + rank] = (float)t;   // tgt_idx
    }
}

// ---------------------------------------------------------------------------
extern "C" void kernel_launch(void* const* d_in, const int* in_sizes, int n_in,
                              void* d_out, int out_size) {
    const float* pred_logits = 0;
    const float* pred_coords = 0;
    const int*   tgt_labels  = 0;
    const float* tgt_joints  = 0;
    for (int k = 0; k < n_in; k++) {
        switch (in_sizes[k]) {
            case BS * Qn * NCn: pred_logits = (const float*)d_in[k]; break;
            case BS * Qn * 2:   pred_coords = (const float*)d_in[k]; break;
            case BS * Tn:       tgt_labels  = (const int*)  d_in[k]; break;
            case BS * Tn * 2:   tgt_joints  = (const float*)d_in[k]; break;
        }
    }
    float* out = (float*)d_out;

    softmax_kernel<<<BS, 256>>>(pred_logits);
    cost_kernel<<<dim3(Tn, BS), 256>>>(pred_coords, tgt_labels, tgt_joints);
    lsa_kernel<<<BS, 32>>>(out);
}

// round 16
// speedup vs baseline: 7.8466x; 7.8466x over previous
#include <cuda_runtime.h>
#include <math.h>

#define BS 64
#define Qn 1024
#define Tn 128
#define NCn 20
#define FINF 1e30f
#define NT 256          // threads per LSA block
#define CPT 4           // contiguous columns per thread (Qn / NT)

// Scratch (allocation-free rule: __device__ globals)
__device__ float g_prob[(size_t)BS * NCn * Qn];   // softmax probs, transposed (b, c, q)
__device__ float g_cost[(size_t)BS * Tn * Qn];    // cost, rows = targets, cols = queries

// ---------------------------------------------------------------------------
// XLA:CPU GenerateVF32Exp (Cephes/Eigen constants, HORNER) with LLVM FMA
// contraction as emitted on aarch64 (fmla/fmls). (VERIFIED bit-exact vs ref.)
// ---------------------------------------------------------------------------
__device__ __forceinline__ float expf_xla_fma(float x) {
    const float half   = 0.5f;
    const float one    = 1.0f;
    const float exp_hi = 88.3762626647950f;
    const float exp_lo = -88.3762626647949f;
    const float LOG2EF = 1.44269504088896341f;
    const float C1     = 0.693359375f;
    const float C2     = -2.12194440e-4f;
    const float p0     = 1.9875691500E-4f;
    const float p1     = 1.3981999507E-3f;
    const float p2     = 8.3334519073E-3f;
    const float p3     = 4.1665795894E-2f;
    const float p4     = 1.6666665459E-1f;
    const float p5     = 5.0000001201E-1f;

    float xc = fminf(fmaxf(x, exp_lo), exp_hi);
    float fx = floorf(__fmaf_rn(xc, LOG2EF, half));
    float xr = __fmaf_rn(-fx, C1, xc);
    xr       = __fmaf_rn(-fx, C2, xr);
    float z  = __fmul_rn(xr, xr);

    float y = __fmaf_rn(p0, xr, p1);
    y = __fmaf_rn(y, xr, p2);
    y = __fmaf_rn(y, xr, p3);
    y = __fmaf_rn(y, xr, p4);
    y = __fmaf_rn(y, xr, p5);
    y = __fmaf_rn(y, z, xr);
    y = __fadd_rn(y, one);

    int emm0 = ((int)fx + 127) << 23;
    float pow2 = __int_as_float(emm0);
    return fmaxf(__fmul_rn(y, pow2), x);
}

// ---------------------------------------------------------------------------
// Kernel A: softmax (VERIFIED): Cephes-FMA exp, VF4 partials + FADDP hsum,
// IEEE division. Stored transposed (b, class, q).
// ---------------------------------------------------------------------------
__global__ void softmax_kernel(const float* __restrict__ logits) {
    int b = blockIdx.x;
    for (int q = threadIdx.x; q < Qn; q += blockDim.x) {
        const float* l = logits + ((size_t)b * Qn + q) * NCn;
        float lv[NCn];
        float m = -FINF;
#pragma unroll
        for (int c = 0; c < NCn; c++) { lv[c] = l[c]; m = fmaxf(m, lv[c]); }
#pragma unroll
        for (int c = 0; c < NCn; c++)
            lv[c] = expf_xla_fma(__fsub_rn(lv[c], m));

        float a0 = lv[0], a1 = lv[1], a2 = lv[2], a3 = lv[3];
#pragma unroll
        for (int i = 1; i < 5; i++) {
            a0 = __fadd_rn(a0, lv[4 * i + 0]);
            a1 = __fadd_rn(a1, lv[4 * i + 1]);
            a2 = __fadd_rn(a2, lv[4 * i + 2]);
            a3 = __fadd_rn(a3, lv[4 * i + 3]);
        }
        float s = __fadd_rn(__fadd_rn(a0, a1), __fadd_rn(a2, a3));  // FADDP order

#pragma unroll
        for (int c = 0; c < NCn; c++)
            g_prob[((size_t)b * NCn + c) * Qn + q] = __fdiv_rn(lv[c], s);
    }
}

// ---------------------------------------------------------------------------
// Kernel B: cost[b][t][q] = (|pcx-tx| + |pcy-ty|) - prob[b][label_t][q]
// ---------------------------------------------------------------------------
__global__ void cost_kernel(const float* __restrict__ pred_coords,
                            const int*   __restrict__ tgt_labels,
                            const float* __restrict__ tgt_joints) {
    int t = blockIdx.x;
    int b = blockIdx.y;
    float tx  = tgt_joints[((size_t)b * Tn + t) * 2 + 0];
    float ty  = tgt_joints[((size_t)b * Tn + t) * 2 + 1];
    int   lbl = tgt_labels[(size_t)b * Tn + t];
    const float*  pr  = g_prob + ((size_t)b * NCn + lbl) * Qn;
    const float2* pcv = (const float2*)(pred_coords + (size_t)b * Qn * 2);
    float* out = g_cost + ((size_t)b * Tn + t) * Qn;
    for (int q = threadIdx.x; q < Qn; q += blockDim.x) {
        float2 p = pcv[q];
        float bbox = __fadd_rn(fabsf(__fsub_rn(p.x, tx)), fabsf(__fsub_rn(p.y, ty)));
        out[q] = __fsub_rn(bbox, pr[q]);
    }
}

// ---------------------------------------------------------------------------
// Kernel C: per-batch rectangular JV LSA — 256 threads per batch.
// Thread t owns CONTIGUOUS columns 4t..4t+3 (one float4 load per pop).
// Decision sequence identical to the verified 1-warp version:
//   same relax order ((minV + C) - u_i) - v, same lowest-j argmin tie-break,
//   same dual updates, same augmentation.
// ---------------------------------------------------------------------------
__global__ void __launch_bounds__(NT, 1) lsa_kernel(float* __restrict__ out) {
    __shared__ float s_u[Tn];
    __shared__ int   s_col4row[Tn];
    __shared__ int   s_row4col[Qn];
    __shared__ int   s_path[Qn];
    __shared__ float s_pval[NT / 32];
    __shared__ int   s_pidx[NT / 32];
    __shared__ float s_minVal;
    __shared__ int   s_i;
    __shared__ int   s_jstar;

    const int b    = blockIdx.x;
    const int tid  = threadIdx.x;
    const int lane = tid & 31;
    const int wid  = tid >> 5;
    const int j0   = tid * CPT;
    const float* __restrict__ C = g_cost + (size_t)b * Tn * Qn;

    float v[CPT], spc[CPT];
#pragma unroll
    for (int k = 0; k < CPT; k++) v[k] = 0.f;

    for (int j = tid; j < Qn; j += NT) s_row4col[j] = -1;
    if (tid < Tn) { s_u[tid] = 0.f; s_col4row[tid] = -1; }
    __syncthreads();

    for (int cur = 0; cur < Tn; cur++) {
        unsigned SC = 0u;                 // bit k: column j0+k scanned
#pragma unroll
        for (int k = 0; k < CPT; k++) spc[k] = FINF;

        int   i    = cur;
        float minV = 0.f;
        int   sink;

        while (true) {
            const float u_i = s_u[i];
            // one 128-bit L2 load for this thread's 4 columns of row i
            float4 c4 = *(const float4*)(C + (size_t)i * Qn + j0);
            float cv[CPT] = {c4.x, c4.y, c4.z, c4.w};

            float bv = FINF;
            int   bj = 0x7fffffff;
#pragma unroll
            for (int k = 0; k < CPT; k++) {
                if (!((SC >> k) & 1u)) {
                    float r = __fsub_rn(__fsub_rn(__fadd_rn(minV, cv[k]), u_i), v[k]);
                    if (r < spc[k]) { spc[k] = r; s_path[j0 + k] = i; }
                    if (spc[k] < bv) { bv = spc[k]; bj = j0 + k; }  // k asc => lowest j
                }
            }
            // warp-level lexicographic argmin (lowest j on ties)
#pragma unroll
            for (int off = 16; off; off >>= 1) {
                float ov = __shfl_down_sync(0xffffffffu, bv, off);
                int   oj = __shfl_down_sync(0xffffffffu, bj, off);
                if (ov < bv || (ov == bv && oj < bj)) { bv = ov; bj = oj; }
            }
            if (lane == 0) { s_pval[wid] = bv; s_pidx[wid] = bj; }
            __syncthreads();

            // cross-warp reduce (warp 0; lanes >= NT/32 hold identity)
            if (wid == 0) {
                bv = (lane < NT / 32) ? s_pval[lane] : FINF;
                bj = (lane < NT / 32) ? s_pidx[lane] : 0x7fffffff;
#pragma unroll
                for (int off = 4; off; off >>= 1) {
                    float ov = __shfl_down_sync(0xffffffffu, bv, off);
                    int   oj = __shfl_down_sync(0xffffffffu, bj, off);
                    if (ov < bv || (ov == bv && oj < bj)) { bv = ov; bj = oj; }
                }
                if (lane == 0) {
                    s_minVal = bv;
                    s_jstar  = bj;
                    s_i      = s_row4col[bj];
                }
            }
            __syncthreads();

            const int jstar = s_jstar;
            minV = s_minVal;
            if ((jstar >> 2) == tid) SC |= 1u << (jstar & 3);  // owner marks SC
            int inext = s_i;
            if (inext < 0) { sink = jstar; break; }
            i = inext;
        }

        const float minVal = minV;

        // dual updates: v[j] -= minVal - spc[j] for j in SC;
        //               u[row4col[j]] += minVal - spc[j] for assigned j in SC
#pragma unroll
        for (int k = 0; k < CPT; k++) {
            if ((SC >> k) & 1u) {
                float d = __fsub_rn(minVal, spc[k]);
                v[k] = __fsub_rn(v[k], d);
                int r = s_row4col[j0 + k];
                if (r >= 0) s_u[r] = __fadd_rn(s_u[r], d);   // matching: distinct r
            }
        }
        __syncthreads();

        // augment alternating path (thread 0; path is short)
        if (tid == 0) {
            s_u[cur] = __fadd_rn(s_u[cur], minVal);
            int jj = sink;
            while (true) {
                int ii = s_path[jj];
                s_row4col[jj] = ii;
                int nj = s_col4row[ii];
                s_col4row[ii] = jj;
                if (ii == cur) break;
                jj = nj;
            }
        }
        __syncthreads();
    }

    // output: pred_idx = sorted(col4row), tgt_idx = argsort(col4row)
    if (tid < Tn) {
        int c = s_col4row[tid];
        int rank = 0;
#pragma unroll 4
        for (int s = 0; s < Tn; s++) rank += (s_col4row[s] < c);
        out[(size_t)b * Tn + rank]                   = (float)c;   // pred_idx
        out[(size_t)BS * Tn + (size_t)b * Tn + rank] = (float)tid; // tgt_idx
    }
}

// ---------------------------------------------------------------------------
extern "C" void kernel_launch(void* const* d_in, const int* in_sizes, int n_in,
                              void* d_out, int out_size) {
    const float* pred_logits = 0;
    const float* pred_coords = 0;
    const int*   tgt_labels  = 0;
    const float* tgt_joints  = 0;
    for (int k = 0; k < n_in; k++) {
        switch (in_sizes[k]) {
            case BS * Qn * NCn: pred_logits = (const float*)d_in[k]; break;
            case BS * Qn * 2:   pred_coords = (const float*)d_in[k]; break;
            case BS * Tn:       tgt_labels  = (const int*)  d_in[k]; break;
            case BS * Tn * 2:   tgt_joints  = (const float*)d_in[k]; break;
        }
    }
    float* out = (float*)d_out;

    softmax_kernel<<<BS, 256>>>(pred_logits);
    cost_kernel<<<dim3(Tn, BS), 256>>>(pred_coords, tgt_labels, tgt_joints);
    lsa_kernel<<<BS, NT>>>(out);
}